// round 1
// baseline (speedup 1.0000x reference)
#include <cuda_runtime.h>
#include <cstdint>

#define M_ROWS 65536
#define B_ROWS 2048
#define DD 13

// ---- shared-memory layout for k_mlp (float offsets) ----
#define OFF_W1   0        // [300][16]  (W1 rows padded to 16 for LDS.128)
#define OFF_B1   4800     // [300]
#define OFF_B2   5100     // [600]
#define OFF_B3   5700     // [112] (zero pad >=100)
#define OFF_B4   5812     // [14]  (zero pad >=13) ; pad to 5828
#define OFF_H1   5828     // [64][308]  h1, row-major, stride 308 (conflict-free LDS.128)
#define OFF_W2C  25540    // [40][300]  W2 chunk, row-major
#define OFF_H2C  37540    // [64][44]   h2 chunk, stride 44 (conflict-free LDS.128)
#define OFF_W3C  40356    // [112][40]  W3 chunk, c-major (zero pad c>=100)
#define OFF_W4   44836    // [13][112]  W4 (zero pad c>=100)
#define SMEM_FLOATS 46292
#define SMEM_BYTES  (SMEM_FLOATS * 4)

// ---- global scratch (static __device__: no allocation) ----
__device__ float g_t1n[M_ROWS * DD];
__device__ float g_t2n[B_ROWS * DD];
__device__ int   g_maxkey[B_ROWS];

// ---- packed f32x2 helpers ----
__device__ __forceinline__ unsigned long long pk2(float lo, float hi) {
    unsigned long long r;
    asm("mov.b64 %0, {%1,%2};" : "=l"(r) : "f"(lo), "f"(hi));
    return r;
}
__device__ __forceinline__ void upk2(unsigned long long v, float& lo, float& hi) {
    asm("mov.b64 {%0,%1}, %2;" : "=f"(lo), "=f"(hi) : "l"(v));
}
__device__ __forceinline__ void fma2(unsigned long long& d, unsigned long long a,
                                     unsigned long long b) {
    asm("fma.rn.f32x2 %0, %1, %2, %0;" : "+l"(d) : "l"(a), "l"(b));
}

// ---- monotone float<->int key for atomicMax ----
__device__ __forceinline__ int fkey(float f) {
    int i = __float_as_int(f);
    return (i >= 0) ? i : (i ^ 0x7FFFFFFF);
}
__device__ __forceinline__ float finv(int k) {
    return __int_as_float((k >= 0) ? k : (k ^ 0x7FFFFFFF));
}

// ============================================================
// k_pre: normalize value -> g_t2n, init g_maxkey
// ============================================================
__global__ void k_pre(const float* __restrict__ value) {
    int idx = blockIdx.x * blockDim.x + threadIdx.x;
    if (idx < B_ROWS) {
        float v[DD];
        float ss = 0.f;
#pragma unroll
        for (int d = 0; d < DD; d++) { v[d] = value[idx * DD + d]; ss += v[d] * v[d]; }
        float inv = 1.0f / fmaxf(sqrtf(ss), 1e-8f);
#pragma unroll
        for (int d = 0; d < DD; d++) g_t2n[idx * DD + d] = v[d] * inv;
        g_maxkey[idx] = fkey(-3.0e38f);
    }
}

// ============================================================
// k_mlp: fully fused 4-layer MLP + row normalize -> g_t1n
// One block = 64 rows, 256 threads, ~181KB dynamic smem.
// ============================================================
__global__ void __launch_bounds__(256)
k_mlp(const float* __restrict__ memory,
      const float* __restrict__ W1, const float* __restrict__ b1,
      const float* __restrict__ W2, const float* __restrict__ b2,
      const float* __restrict__ W3, const float* __restrict__ b3,
      const float* __restrict__ W4, const float* __restrict__ b4) {
    extern __shared__ float sm[];
    const int t = threadIdx.x;
    const int row0 = blockIdx.x * 64;
    const int m63 = t & 63;       // row within tile
    const int g4  = t >> 6;       // 0..3  (j-group for L2, c-group for L3/L4)
    const int c0  = g4 * 28;      // L3 column base (28 cols per thread, padded to 112)

    // ---- cooperative weight/bias staging ----
    for (int i = t; i < 300 * DD; i += 256) {
        int k = i / DD, d = i % DD;
        sm[OFF_W1 + k * 16 + d] = W1[i];
    }
    for (int i = t; i < 300; i += 256) sm[OFF_B1 + i] = b1[i];
    for (int i = t; i < 600; i += 256) sm[OFF_B2 + i] = b2[i];
    for (int i = t; i < 112; i += 256) sm[OFF_B3 + i] = (i < 100) ? b3[i] : 0.f;
    if (t < 14) sm[OFF_B4 + t] = (t < DD) ? b4[t] : 0.f;
    for (int i = t; i < 13 * 112; i += 256) {
        int d = i / 112, c = i % 112;
        sm[OFF_W4 + i] = (c < 100) ? W4[d * 100 + c] : 0.f;
    }

    // ---- layer 1: h1 = relu(x @ W1^T + b1), h1 in smem [64][308] ----
    {
        float x[DD];
#pragma unroll
        for (int d = 0; d < DD; d++) x[d] = memory[(row0 + m63) * DD + d];
        __syncthreads();  // W1/b1 staged
        const int k0 = g4 * 75;
        for (int k = k0; k < k0 + 75; k++) {
            const float* wr = sm + OFF_W1 + k * 16;
            float acc = sm[OFF_B1 + k];
#pragma unroll
            for (int d = 0; d < DD; d++) acc += x[d] * wr[d];
            sm[OFF_H1 + m63 * 308 + k] = fmaxf(acc, 0.f);
        }
    }
    __syncthreads();

    // persistent h3 accumulators: 28 cols, f32x2 even/odd-j split halves
    unsigned long long acc3[28];
#pragma unroll
    for (int i = 0; i < 28; i++) acc3[i] = 0ull;

    // ---- fused layers 2+3 over 15 chunks of 40 h2-columns ----
    for (int ch = 0; ch < 15; ch++) {
        // stage W2 chunk [40][300] (contiguous in global)
        const float* W2g = W2 + ch * 40 * 300;
        for (int i = t * 4; i < 12000; i += 1024)
            *reinterpret_cast<float4*>(sm + OFF_W2C + i) =
                *reinterpret_cast<const float4*>(W2g + i);
        // stage W3 chunk c-major [112][40], zero pad c>=100
        for (int i4 = t; i4 < 1120; i4 += 256) {
            int c = i4 / 10, jq = (i4 % 10) * 4;
            float4 v = make_float4(0.f, 0.f, 0.f, 0.f);
            if (c < 100) v = *reinterpret_cast<const float4*>(W3 + c * 600 + ch * 40 + jq);
            *reinterpret_cast<float4*>(sm + OFF_W3C + c * 40 + jq) = v;
        }
        __syncthreads();

        // layer 2: h2[m][j] for j in this chunk (thread: 10 j's, k-split f32x2)
        {
            unsigned long long a2[10];
#pragma unroll
            for (int i = 0; i < 10; i++) a2[i] = 0ull;
            const float* hrow  = sm + OFF_H1 + m63 * 308;
            const float* wbase = sm + OFF_W2C + (g4 * 10) * 300;
#pragma unroll 3
            for (int k = 0; k < 300; k += 4) {
                ulonglong2 h = *reinterpret_cast<const ulonglong2*>(hrow + k);
#pragma unroll
                for (int jj = 0; jj < 10; jj++) {
                    ulonglong2 w = *reinterpret_cast<const ulonglong2*>(wbase + jj * 300 + k);
                    fma2(a2[jj], h.x, w.x);
                    fma2(a2[jj], h.y, w.y);
                }
            }
#pragma unroll
            for (int jj = 0; jj < 10; jj++) {
                float lo, hi;
                upk2(a2[jj], lo, hi);
                float z = lo + hi + sm[OFF_B2 + ch * 40 + g4 * 10 + jj];
                sm[OFF_H2C + m63 * 44 + g4 * 10 + jj] = (z > 0.f) ? z : 0.01f * z;
            }
        }
        __syncthreads();

        // layer 3 accumulate: acc3[c] += h2 @ W3chunk^T  (thread: 28 c's, j-split f32x2)
        {
            const float* h2row  = sm + OFF_H2C + m63 * 44;
            const float* w3base = sm + OFF_W3C + c0 * 40;
#pragma unroll 2
            for (int j = 0; j < 40; j += 4) {
                ulonglong2 h = *reinterpret_cast<const ulonglong2*>(h2row + j);
#pragma unroll
                for (int cc = 0; cc < 28; cc++) {
                    ulonglong2 w = *reinterpret_cast<const ulonglong2*>(w3base + cc * 40 + j);
                    fma2(acc3[cc], h.x, w.x);
                    fma2(acc3[cc], h.y, w.y);
                }
            }
        }
        __syncthreads();
    }

    // ---- layer 4 partials (c-split f32x2 over this thread's 28 h3 cols) ----
    float h3v[28];
#pragma unroll
    for (int cc = 0; cc < 28; cc++) {
        float lo, hi;
        upk2(acc3[cc], lo, hi);
        float z = lo + hi + sm[OFF_B3 + c0 + cc];
        h3v[cc] = fmaxf(z, 0.f);
    }
    unsigned long long pd[DD];
#pragma unroll
    for (int d = 0; d < DD; d++) pd[d] = 0ull;
#pragma unroll
    for (int cp = 0; cp < 14; cp++) {
        unsigned long long hp = pk2(h3v[2 * cp], h3v[2 * cp + 1]);
#pragma unroll
        for (int d = 0; d < DD; d++)
            fma2(pd[d], hp,
                 *reinterpret_cast<const unsigned long long*>(sm + OFF_W4 + d * 112 + c0 + 2 * cp));
    }
    // write partials into sH1 region (all h1 reads are behind the last barrier)
#pragma unroll
    for (int d = 0; d < DD; d++) {
        float lo, hi;
        upk2(pd[d], lo, hi);
        sm[OFF_H1 + (m63 * 4 + g4) * 14 + d] = lo + hi;
    }
    __syncthreads();

    // ---- reduce partials, leaky, normalize, write t1n ----
    if (t < 64) {
        float t1v[DD];
        float ss = 0.f;
#pragma unroll
        for (int d = 0; d < DD; d++) {
            float s_ = sm[OFF_H1 + (t * 4 + 0) * 14 + d]
                     + sm[OFF_H1 + (t * 4 + 1) * 14 + d]
                     + sm[OFF_H1 + (t * 4 + 2) * 14 + d]
                     + sm[OFF_H1 + (t * 4 + 3) * 14 + d];
            s_ += sm[OFF_B4 + d];
            float v = (s_ > 0.f) ? s_ : 0.01f * s_;
            t1v[d] = v;
            ss += v * v;
        }
        float inv = 1.0f / fmaxf(sqrtf(ss), 1e-8f);
#pragma unroll
        for (int d = 0; d < DD; d++)
            g_t1n[(row0 + t) * DD + d] = t1v[d] * inv;
    }
}

// ============================================================
// k_sim: per-b running max of t2n . t1n over a 512-row m tile
// grid (128 m-tiles, 8 b-groups), 256 threads (1 b each)
// ============================================================
__global__ void __launch_bounds__(256) k_sim() {
    __shared__ float sT[DD * 512];  // d-major: sT[d*512 + m]
    const int t  = threadIdx.x;
    const int m0 = blockIdx.x * 512;
    const int b  = blockIdx.y * 256 + t;

    for (int i = t; i < 512 * DD; i += 256) {
        int mm = i / DD, d = i % DD;
        sT[d * 512 + mm] = g_t1n[(m0 + mm) * DD + d];
    }
    unsigned long long q[DD];
#pragma unroll
    for (int d = 0; d < DD; d++) {
        float v = g_t2n[b * DD + d];
        q[d] = pk2(v, v);
    }
    __syncthreads();

    float mx = -3.0e38f;
#pragma unroll 2
    for (int mp = 0; mp < 512; mp += 2) {
        unsigned long long acc = 0ull;
#pragma unroll
        for (int d = 0; d < DD; d++)
            fma2(acc, q[d], *reinterpret_cast<const unsigned long long*>(&sT[d * 512 + mp]));
        float lo, hi;
        upk2(acc, lo, hi);
        mx = fmaxf(mx, fmaxf(lo, hi));
    }
    atomicMax(&g_maxkey[b], fkey(mx));
}

// ============================================================
// k_fin: decode keys, apply SCALE
// ============================================================
__global__ void k_fin(float* __restrict__ out) {
    int b = blockIdx.x * blockDim.x + threadIdx.x;
    if (b < B_ROWS) out[b] = 23.0f * finv(g_maxkey[b]);
}

// ============================================================
extern "C" void kernel_launch(void* const* d_in, const int* in_sizes, int n_in,
                              void* d_out, int out_size) {
    const float* memory = (const float*)d_in[0];
    const float* value  = (const float*)d_in[1];
    const float* W1 = (const float*)d_in[2];
    const float* b1 = (const float*)d_in[3];
    const float* W2 = (const float*)d_in[4];
    const float* b2 = (const float*)d_in[5];
    const float* W3 = (const float*)d_in[6];
    const float* b3 = (const float*)d_in[7];
    const float* W4 = (const float*)d_in[8];
    const float* b4 = (const float*)d_in[9];

    cudaFuncSetAttribute(k_mlp, cudaFuncAttributeMaxDynamicSharedMemorySize, SMEM_BYTES);

    k_pre<<<8, 256>>>(value);
    k_mlp<<<1024, 256, SMEM_BYTES>>>(memory, W1, b1, W2, b2, W3, b3, W4, b4);
    k_sim<<<dim3(128, 8), 256>>>();
    k_fin<<<8, 256>>>((float*)d_out);
}